// round 1
// baseline (speedup 1.0000x reference)
#include <cuda_runtime.h>
#include <math.h>

// KANLayer: IN=128, OUT=128, SIZE=16384, BATCH=1024, NUM=5, K=3 -> 8 basis fns, 12 knots.
// Outputs (flattened in tuple order): y_out[1024*128], preacts[1024*128*128],
// postacts[1024*128*128], postspline[1024*128*128].
//
// Key facts exploited:
//  - xe[s,b] = x[b, s % IN]  (s = o*IN + i), so basis B_j depends only on (b, i).
//  - preacts[b,o,i] = x[b,i]; postspline[b,o,i] = dot(coef[o*IN+i,:], B(b,i));
//    postacts = mask*(scale_base*silu(x) + scale_sp*spline); y_out = sum_i postacts.
// Kernel is HBM-write-bound (~202 MB of stores).

#define IN_DIM   128
#define OUT_DIM  128
#define BATCHSZ  1024
#define NB       8     // NUM + K basis functions
#define NKNOT    12    // NUM+1 extended by K each side
#define TILE_B   16
#define TILE_O   8
#define NTHREADS 256

#define SMEM_FLOATS (NB * TILE_B * IN_DIM + 2 * TILE_B * IN_DIM)
#define SMEM_BYTES  (SMEM_FLOATS * 4)

__global__ __launch_bounds__(NTHREADS, 2)
void kan_kernel(const float* __restrict__ x,
                const float* __restrict__ grid,
                const float* __restrict__ coef,
                const float* __restrict__ scale_base,
                const float* __restrict__ scale_sp,
                const float* __restrict__ mask,
                float* __restrict__ out)
{
    extern __shared__ float smem[];
    float* Bsh   = smem;                              // [NB][TILE_B][IN_DIM]
    float* xsh   = Bsh + NB * TILE_B * IN_DIM;        // [TILE_B][IN_DIM]
    float* silsh = xsh + TILE_B * IN_DIM;             // [TILE_B][IN_DIM]

    const int b0  = blockIdx.x * TILE_B;
    const int o0  = blockIdx.y * TILE_O;
    const int tid = threadIdx.x;

    // ---------------- Phase B: basis for (b, i) pairs ----------------
    for (int p = tid; p < TILE_B * IN_DIM; p += NTHREADS) {
        const int b = p >> 7;        // /128
        const int i = p & 127;
        const float xv = x[(b0 + b) * IN_DIM + i];

        // Extended knot vector from grid row i (all rows identical by construction,
        // but we read the actual data). Sequential +-h to match reference fp order.
        float t[NKNOT];
        t[3] = grid[i * 6 + 0];
        t[4] = grid[i * 6 + 1];
        t[5] = grid[i * 6 + 2];
        t[6] = grid[i * 6 + 3];
        t[7] = grid[i * 6 + 4];
        t[8] = grid[i * 6 + 5];
        const float h = (t[8] - t[3]) * 0.2f;
        t[2] = t[3] - h;  t[1] = t[2] - h;  t[0] = t[1] - h;
        t[9] = t[8] + h;  t[10] = t[9] + h; t[11] = t[10] + h;

        float Bv[NKNOT - 1];
        #pragma unroll
        for (int m = 0; m < NKNOT - 1; m++)
            Bv[m] = (xv >= t[m] && xv < t[m + 1]) ? 1.0f : 0.0f;

        #pragma unroll
        for (int pd = 1; pd <= 3; pd++) {
            #pragma unroll
            for (int m = 0; m < NKNOT - 1 - 3; m++) { // conservative upper bound below
                // valid range: m < (NKNOT-1) - pd
                if (m < (NKNOT - 1) - pd) {
                    Bv[m] = (xv - t[m]) / (t[m + pd] - t[m]) * Bv[m]
                          + (t[m + pd + 1] - xv) / (t[m + pd + 1] - t[m + 1]) * Bv[m + 1];
                }
            }
            // remaining entries of this level (m from NKNOT-4 .. NKNOT-2-pd)
            #pragma unroll
            for (int m = NKNOT - 1 - 3; m < NKNOT - 2; m++) {
                if (m < (NKNOT - 1) - pd) {
                    Bv[m] = (xv - t[m]) / (t[m + pd] - t[m]) * Bv[m]
                          + (t[m + pd + 1] - xv) / (t[m + pd + 1] - t[m + 1]) * Bv[m + 1];
                }
            }
        }

        #pragma unroll
        for (int j = 0; j < NB; j++)
            Bsh[(j * TILE_B + b) * IN_DIM + i] = Bv[j];
        xsh[b * IN_DIM + i]   = xv;
        silsh[b * IN_DIM + i] = xv / (1.0f + expf(-xv));
    }
    __syncthreads();

    // ---------------- Compute + store phase ----------------
    const int warp = tid >> 5;
    const int lane = tid & 31;
    const int o    = o0 + warp;       // TILE_O == warps per block

    // coef + scales for this warp's o, lane's 4 i's, into registers
    float cf[4][NB], sb[4], ss[4], mk[4];
    #pragma unroll
    for (int q = 0; q < 4; q++) {
        const int i = lane + 32 * q;
        const int s = o * IN_DIM + i;
        #pragma unroll
        for (int j = 0; j < NB; j++)
            cf[q][j] = coef[s * NB + j];
        sb[q] = scale_base[s];
        ss[q] = scale_sp[s];
        mk[q] = mask[s];
    }

    const size_t P = (size_t)BATCHSZ * OUT_DIM * IN_DIM;
    float* y_out      = out;
    float* preacts    = out + (size_t)BATCHSZ * OUT_DIM;
    float* postacts   = preacts + P;
    float* postspline = postacts + P;

    for (int b = 0; b < TILE_B; b++) {
        const int bg = b0 + b;
        const size_t base = ((size_t)bg * OUT_DIM + o) * IN_DIM;
        float acc = 0.0f;
        #pragma unroll
        for (int q = 0; q < 4; q++) {
            const int i = lane + 32 * q;
            float sp = 0.0f;
            #pragma unroll
            for (int j = 0; j < NB; j++)
                sp += cf[q][j] * Bsh[(j * TILE_B + b) * IN_DIM + i];
            const float xv = xsh[b * IN_DIM + i];
            const float y  = mk[q] * (sb[q] * silsh[b * IN_DIM + i] + ss[q] * sp);
            postspline[base + i] = sp;
            postacts[base + i]   = y;
            preacts[base + i]    = xv;
            acc += y;
        }
        // warp-reduce acc over 32 lanes (sum over all 128 i)
        #pragma unroll
        for (int off = 16; off > 0; off >>= 1)
            acc += __shfl_down_sync(0xffffffffu, acc, off);
        if (lane == 0)
            y_out[bg * OUT_DIM + o] = acc;
    }
}

extern "C" void kernel_launch(void* const* d_in, const int* in_sizes, int n_in,
                              void* d_out, int out_size)
{
    const float* x          = (const float*)d_in[0];
    const float* grid       = (const float*)d_in[1];
    const float* coef       = (const float*)d_in[2];
    const float* scale_base = (const float*)d_in[3];
    const float* scale_sp   = (const float*)d_in[4];
    const float* mask       = (const float*)d_in[5];
    float* out = (float*)d_out;

    cudaFuncSetAttribute(kan_kernel,
                         cudaFuncAttributeMaxDynamicSharedMemorySize, SMEM_BYTES);

    dim3 g(BATCHSZ / TILE_B, OUT_DIM / TILE_O);
    kan_kernel<<<g, NTHREADS, SMEM_BYTES>>>(x, grid, coef, scale_base,
                                            scale_sp, mask, out);
}

// round 2
// speedup vs baseline: 1.7733x; 1.7733x over previous
#include <cuda_runtime.h>
#include <math.h>

// KANLayer: IN=128, OUT=128, SIZE=16384, BATCH=1024, NUM=5, K=3 -> 8 basis fns.
// Outputs flattened: y_out[1024*128], preacts[1024*128*128],
// postacts[...], postspline[...].
//
// Two-kernel design:
//   K1: basis per (b,i) computed ONCE (131K evals, was 16x redundant) -> g_basis,
//       plus silu(x) -> g_silu.
//   K2: streaming compute. lane owns i = 4*lane+{0..3} => float4 stores (STG.128),
//       basis via conflict-free LDS.128 from smem tile, coef/scales in registers.

#define IN_DIM   128
#define OUT_DIM  128
#define BATCHSZ  1024
#define NB       8
#define NKNOT    12
#define TILE_B   8
#define TILE_O   8
#define NTHREADS 256

__device__ float g_basis[BATCHSZ * NB * IN_DIM];   // [b][j][i]  (4 MB)
__device__ float g_silu [BATCHSZ * IN_DIM];        // [b][i]

// ---------------------------------------------------------------------------
// Kernel 1: Cox-de-Boor basis, one thread per (b,i).
// ---------------------------------------------------------------------------
__global__ __launch_bounds__(256)
void kan_basis_kernel(const float* __restrict__ x,
                      const float* __restrict__ grid)
{
    const int p = blockIdx.x * 256 + threadIdx.x;   // 0 .. 131071
    if (p >= BATCHSZ * IN_DIM) return;
    const int i  = p & (IN_DIM - 1);
    const float xv = x[p];

    // Extended knot vector (sequential +-h to match reference fp order).
    float t[NKNOT];
    t[3] = grid[i * 6 + 0];
    t[4] = grid[i * 6 + 1];
    t[5] = grid[i * 6 + 2];
    t[6] = grid[i * 6 + 3];
    t[7] = grid[i * 6 + 4];
    t[8] = grid[i * 6 + 5];
    const float h = (t[8] - t[3]) * 0.2f;
    t[2] = t[3] - h;  t[1] = t[2] - h;  t[0]  = t[1]  - h;
    t[9] = t[8] + h;  t[10] = t[9] + h; t[11] = t[10] + h;

    float Bv[NKNOT - 1];
    #pragma unroll
    for (int m = 0; m < NKNOT - 1; m++)
        Bv[m] = (xv >= t[m] && xv < t[m + 1]) ? 1.0f : 0.0f;

    #pragma unroll
    for (int pd = 1; pd <= 3; pd++) {
        #pragma unroll
        for (int m = 0; m < NKNOT - 2; m++) {
            if (m < (NKNOT - 1) - pd) {
                Bv[m] = (xv - t[m]) / (t[m + pd] - t[m]) * Bv[m]
                      + (t[m + pd + 1] - xv) / (t[m + pd + 1] - t[m + 1]) * Bv[m + 1];
            }
        }
    }

    const int b = p >> 7;
    #pragma unroll
    for (int j = 0; j < NB; j++)
        g_basis[(b * NB + j) * IN_DIM + i] = Bv[j];
    g_silu[p] = xv / (1.0f + expf(-xv));
}

// ---------------------------------------------------------------------------
// Kernel 2: main streaming compute.
// ---------------------------------------------------------------------------
__global__ __launch_bounds__(NTHREADS, 3)
void kan_main_kernel(const float* __restrict__ x,
                     const float* __restrict__ coef,
                     const float* __restrict__ scale_base,
                     const float* __restrict__ scale_sp,
                     const float* __restrict__ mask,
                     float* __restrict__ out)
{
    __shared__ float4 Bsh[TILE_B][NB][IN_DIM / 4];   // [b][j][L]
    __shared__ float4 xsh[TILE_B][IN_DIM / 4];
    __shared__ float4 ssh[TILE_B][IN_DIM / 4];

    const int b0 = blockIdx.x * TILE_B;
    const int o  = blockIdx.y * TILE_O + (threadIdx.x >> 5);
    const int L  = threadIdx.x & 31;

    // ---- stage basis / x / silu tiles (coalesced float4 copies) ----
    {
        const float4* gb = (const float4*)(g_basis + b0 * NB * IN_DIM);
        float4* db = &Bsh[0][0][0];
        #pragma unroll
        for (int idx = threadIdx.x; idx < TILE_B * NB * (IN_DIM / 4); idx += NTHREADS)
            db[idx] = gb[idx];
        const float4* gx = (const float4*)(x + b0 * IN_DIM);
        const float4* gs = (const float4*)(g_silu + b0 * IN_DIM);
        float4* dx = &xsh[0][0];
        float4* ds = &ssh[0][0];
        #pragma unroll
        for (int idx = threadIdx.x; idx < TILE_B * (IN_DIM / 4); idx += NTHREADS) {
            dx[idx] = gx[idx];
            ds[idx] = gs[idx];
        }
    }

    // ---- per-warp constants: coef + scales for o, i = 4L..4L+3 ----
    float cf[4][NB];
    float4 sb, ss, mk;
    {
        const int ibase = 4 * L;
        #pragma unroll
        for (int r = 0; r < 4; r++) {
            const int s = o * IN_DIM + ibase + r;
            const float4 a = *(const float4*)(coef + s * NB);
            const float4 b4 = *(const float4*)(coef + s * NB + 4);
            cf[r][0] = a.x;  cf[r][1] = a.y;  cf[r][2] = a.z;  cf[r][3] = a.w;
            cf[r][4] = b4.x; cf[r][5] = b4.y; cf[r][6] = b4.z; cf[r][7] = b4.w;
        }
        sb = *(const float4*)(scale_base + o * IN_DIM + ibase);
        ss = *(const float4*)(scale_sp   + o * IN_DIM + ibase);
        mk = *(const float4*)(mask       + o * IN_DIM + ibase);
    }

    __syncthreads();

    const size_t P = (size_t)BATCHSZ * OUT_DIM * IN_DIM;
    float* y_out      = out;
    float* preacts    = out + (size_t)BATCHSZ * OUT_DIM;
    float* postacts   = preacts + P;
    float* postspline = postacts + P;

    #pragma unroll
    for (int b = 0; b < TILE_B; b++) {
        const int bg = b0 + b;
        float4 sp = make_float4(0.f, 0.f, 0.f, 0.f);
        #pragma unroll
        for (int j = 0; j < NB; j++) {
            const float4 bv = Bsh[b][j][L];
            sp.x = fmaf(cf[0][j], bv.x, sp.x);
            sp.y = fmaf(cf[1][j], bv.y, sp.y);
            sp.z = fmaf(cf[2][j], bv.z, sp.z);
            sp.w = fmaf(cf[3][j], bv.w, sp.w);
        }
        const float4 xv = xsh[b][L];
        const float4 sl = ssh[b][L];
        float4 y;
        y.x = mk.x * fmaf(ss.x, sp.x, sb.x * sl.x);
        y.y = mk.y * fmaf(ss.y, sp.y, sb.y * sl.y);
        y.z = mk.z * fmaf(ss.z, sp.z, sb.z * sl.z);
        y.w = mk.w * fmaf(ss.w, sp.w, sb.w * sl.w);

        const size_t base = ((size_t)bg * OUT_DIM + o) * IN_DIM + 4 * L;
        *(float4*)(preacts    + base) = xv;
        *(float4*)(postacts   + base) = y;
        *(float4*)(postspline + base) = sp;

        float acc = (y.x + y.y) + (y.z + y.w);
        #pragma unroll
        for (int off = 16; off > 0; off >>= 1)
            acc += __shfl_down_sync(0xffffffffu, acc, off);
        if (L == 0)
            y_out[bg * OUT_DIM + o] = acc;
    }
}

// ---------------------------------------------------------------------------
extern "C" void kernel_launch(void* const* d_in, const int* in_sizes, int n_in,
                              void* d_out, int out_size)
{
    const float* x          = (const float*)d_in[0];
    const float* grid       = (const float*)d_in[1];
    const float* coef       = (const float*)d_in[2];
    const float* scale_base = (const float*)d_in[3];
    const float* scale_sp   = (const float*)d_in[4];
    const float* mask       = (const float*)d_in[5];
    float* out = (float*)d_out;

    kan_basis_kernel<<<(BATCHSZ * IN_DIM + 255) / 256, 256>>>(x, grid);

    dim3 g(BATCHSZ / TILE_B, OUT_DIM / TILE_O);
    kan_main_kernel<<<g, NTHREADS>>>(x, coef, scale_base, scale_sp, mask, out);
}

// round 4
// speedup vs baseline: 2.0583x; 1.1607x over previous
#include <cuda_runtime.h>
#include <math.h>

// KANLayer: IN=128, OUT=128, SIZE=16384, BATCH=1024, NUM=5, K=3 -> 8 basis fns.
// K1: basis per (b,i) once -> g_basis (4MB, L2-resident), silu -> g_silu.
// K2: streaming; warp computes TWO outputs (o, o+8) per basis read (Q=2),
//     lane owns i-quad 4L..4L+3 => all streams are STG.128.

#define IN_DIM   128
#define OUT_DIM  128
#define BATCHSZ  1024
#define NB       8
#define NKNOT    12
#define TILE_B   8
#define NTHREADS 256

__device__ float g_basis[BATCHSZ * NB * IN_DIM];   // [b][j][i]
__device__ float g_silu [BATCHSZ * IN_DIM];        // [b][i]

// ---------------------------------------------------------------------------
// Kernel 1: Cox-de-Boor basis, one thread per (b,i). Fast-math divides.
// ---------------------------------------------------------------------------
__global__ __launch_bounds__(256)
void kan_basis_kernel(const float* __restrict__ x,
                      const float* __restrict__ grid)
{
    const int p = blockIdx.x * 256 + threadIdx.x;
    if (p >= BATCHSZ * IN_DIM) return;
    const int i  = p & (IN_DIM - 1);
    const float xv = x[p];

    float t[NKNOT];
    t[3] = grid[i * 6 + 0];
    t[4] = grid[i * 6 + 1];
    t[5] = grid[i * 6 + 2];
    t[6] = grid[i * 6 + 3];
    t[7] = grid[i * 6 + 4];
    t[8] = grid[i * 6 + 5];
    const float h = (t[8] - t[3]) * 0.2f;
    t[2] = t[3] - h;  t[1] = t[2] - h;  t[0]  = t[1]  - h;
    t[9] = t[8] + h;  t[10] = t[9] + h; t[11] = t[10] + h;

    float Bv[NKNOT - 1];
    #pragma unroll
    for (int m = 0; m < NKNOT - 1; m++)
        Bv[m] = (xv >= t[m] && xv < t[m + 1]) ? 1.0f : 0.0f;

    #pragma unroll
    for (int pd = 1; pd <= 3; pd++) {
        #pragma unroll
        for (int m = 0; m < NKNOT - 2; m++) {
            if (m < (NKNOT - 1) - pd) {
                const float a = __fdividef(xv - t[m],          t[m + pd] - t[m]);
                const float c = __fdividef(t[m + pd + 1] - xv, t[m + pd + 1] - t[m + 1]);
                Bv[m] = a * Bv[m] + c * Bv[m + 1];
            }
        }
    }

    const int b = p >> 7;
    #pragma unroll
    for (int j = 0; j < NB; j++)
        g_basis[(b * NB + j) * IN_DIM + i] = Bv[j];
    g_silu[p] = __fdividef(xv, 1.0f + __expf(-xv));
}

// ---------------------------------------------------------------------------
// Kernel 2: main streaming compute. 8 warps; warp w -> outputs (o0+w, o0+8+w).
// ---------------------------------------------------------------------------
__global__ __launch_bounds__(NTHREADS, 2)
void kan_main_kernel(const float* __restrict__ x,
                     const float* __restrict__ coef,
                     const float* __restrict__ scale_base,
                     const float* __restrict__ scale_sp,
                     const float* __restrict__ mask,
                     float* __restrict__ out)
{
    __shared__ float4 Bsh[TILE_B][NB][IN_DIM / 4];
    __shared__ float4 xsh[TILE_B][IN_DIM / 4];
    __shared__ float4 ssh[TILE_B][IN_DIM / 4];

    const int b0   = blockIdx.x * TILE_B;
    const int warp = threadIdx.x >> 5;
    const int L    = threadIdx.x & 31;
    const int oA   = blockIdx.y * 16 + warp;     // first output
    const int oB   = oA + 8;                     // second output

    // ---- stage basis / x / silu tiles ----
    {
        const float4* gb = (const float4*)(g_basis + b0 * NB * IN_DIM);
        float4* db = &Bsh[0][0][0];
        #pragma unroll
        for (int idx = threadIdx.x; idx < TILE_B * NB * (IN_DIM / 4); idx += NTHREADS)
            db[idx] = gb[idx];
        const float4* gx = (const float4*)(x + b0 * IN_DIM);
        const float4* gs = (const float4*)(g_silu + b0 * IN_DIM);
        float4* dx = &xsh[0][0];
        float4* ds = &ssh[0][0];
        #pragma unroll
        for (int idx = threadIdx.x; idx < TILE_B * (IN_DIM / 4); idx += NTHREADS) {
            dx[idx] = gx[idx];
            ds[idx] = gs[idx];
        }
    }

    // ---- per-thread constants for both o's ----
    float cfa[4][NB], cfb[4][NB];
    float4 msbA, mssA, msbB, mssB;
    {
        const int ibase = 4 * L;
        #pragma unroll
        for (int r = 0; r < 4; r++) {
            const int sA = oA * IN_DIM + ibase + r;
            const int sB = oB * IN_DIM + ibase + r;
            float4 a0 = *(const float4*)(coef + sA * NB);
            float4 a1 = *(const float4*)(coef + sA * NB + 4);
            cfa[r][0]=a0.x; cfa[r][1]=a0.y; cfa[r][2]=a0.z; cfa[r][3]=a0.w;
            cfa[r][4]=a1.x; cfa[r][5]=a1.y; cfa[r][6]=a1.z; cfa[r][7]=a1.w;
            float4 b0_ = *(const float4*)(coef + sB * NB);
            float4 b1_ = *(const float4*)(coef + sB * NB + 4);
            cfb[r][0]=b0_.x; cfb[r][1]=b0_.y; cfb[r][2]=b0_.z; cfb[r][3]=b0_.w;
            cfb[r][4]=b1_.x; cfb[r][5]=b1_.y; cfb[r][6]=b1_.z; cfb[r][7]=b1_.w;
        }
        const float4 sbA = *(const float4*)(scale_base + oA * IN_DIM + ibase);
        const float4 spA = *(const float4*)(scale_sp   + oA * IN_DIM + ibase);
        const float4 mkA = *(const float4*)(mask       + oA * IN_DIM + ibase);
        msbA = make_float4(mkA.x*sbA.x, mkA.y*sbA.y, mkA.z*sbA.z, mkA.w*sbA.w);
        mssA = make_float4(mkA.x*spA.x, mkA.y*spA.y, mkA.z*spA.z, mkA.w*spA.w);
        const float4 sbB = *(const float4*)(scale_base + oB * IN_DIM + ibase);
        const float4 spB = *(const float4*)(scale_sp   + oB * IN_DIM + ibase);
        const float4 mkB = *(const float4*)(mask       + oB * IN_DIM + ibase);
        msbB = make_float4(mkB.x*sbB.x, mkB.y*sbB.y, mkB.z*sbB.z, mkB.w*sbB.w);
        mssB = make_float4(mkB.x*spB.x, mkB.y*spB.y, mkB.z*spB.z, mkB.w*spB.w);
    }

    __syncthreads();

    const size_t P = (size_t)BATCHSZ * OUT_DIM * IN_DIM;
    float* y_out      = out;
    float* preacts    = out + (size_t)BATCHSZ * OUT_DIM;
    float* postacts   = preacts + P;
    float* postspline = postacts + P;

    #pragma unroll
    for (int b = 0; b < TILE_B; b++) {
        const int bg = b0 + b;
        float4 spa = make_float4(0.f,0.f,0.f,0.f);
        float4 spb = make_float4(0.f,0.f,0.f,0.f);
        #pragma unroll
        for (int j = 0; j < NB; j++) {
            const float4 bv = Bsh[b][j][L];
            spa.x = fmaf(cfa[0][j], bv.x, spa.x);
            spa.y = fmaf(cfa[1][j], bv.y, spa.y);
            spa.z = fmaf(cfa[2][j], bv.z, spa.z);
            spa.w = fmaf(cfa[3][j], bv.w, spa.w);
            spb.x = fmaf(cfb[0][j], bv.x, spb.x);
            spb.y = fmaf(cfb[1][j], bv.y, spb.y);
            spb.z = fmaf(cfb[2][j], bv.z, spb.z);
            spb.w = fmaf(cfb[3][j], bv.w, spb.w);
        }
        const float4 xv = xsh[b][L];
        const float4 sl = ssh[b][L];
        float4 ya, yb;
        ya.x = fmaf(mssA.x, spa.x, msbA.x * sl.x);
        ya.y = fmaf(mssA.y, spa.y, msbA.y * sl.y);
        ya.z = fmaf(mssA.z, spa.z, msbA.z * sl.z);
        ya.w = fmaf(mssA.w, spa.w, msbA.w * sl.w);
        yb.x = fmaf(mssB.x, spb.x, msbB.x * sl.x);
        yb.y = fmaf(mssB.y, spb.y, msbB.y * sl.y);
        yb.z = fmaf(mssB.z, spb.z, msbB.z * sl.z);
        yb.w = fmaf(mssB.w, spb.w, msbB.w * sl.w);

        const size_t baseA = ((size_t)bg * OUT_DIM + oA) * IN_DIM + 4 * L;
        const size_t baseB = ((size_t)bg * OUT_DIM + oB) * IN_DIM + 4 * L;
        *(float4*)(preacts    + baseA) = xv;
        *(float4*)(postacts   + baseA) = ya;
        *(float4*)(postspline + baseA) = spa;
        *(float4*)(preacts    + baseB) = xv;
        *(float4*)(postacts   + baseB) = yb;
        *(float4*)(postspline + baseB) = spb;

        float accA = (ya.x + ya.y) + (ya.z + ya.w);
        float accB = (yb.x + yb.y) + (yb.z + yb.w);
        #pragma unroll
        for (int off = 16; off > 0; off >>= 1) {
            accA += __shfl_down_sync(0xffffffffu, accA, off);
            accB += __shfl_down_sync(0xffffffffu, accB, off);
        }
        if (L == 0) {
            y_out[bg * OUT_DIM + oA] = accA;
            y_out[bg * OUT_DIM + oB] = accB;
        }
    }
}

// ---------------------------------------------------------------------------
extern "C" void kernel_launch(void* const* d_in, const int* in_sizes, int n_in,
                              void* d_out, int out_size)
{
    const float* x          = (const float*)d_in[0];
    const float* grid       = (const float*)d_in[1];
    const float* coef       = (const float*)d_in[2];
    const float* scale_base = (const float*)d_in[3];
    const float* scale_sp   = (const float*)d_in[4];
    const float* mask       = (const float*)d_in[5];
    float* out = (float*)d_out;

    kan_basis_kernel<<<(BATCHSZ * IN_DIM + 255) / 256, 256>>>(x, grid);

    dim3 g(BATCHSZ / TILE_B, OUT_DIM / 16);
    kan_main_kernel<<<g, NTHREADS>>>(x, coef, scale_base, scale_sp, mask, out);
}